// round 10
// baseline (speedup 1.0000x reference)
#include <cuda_runtime.h>

#define BB 4
#define NN 16384
#define MM 2048
#define CC 64
#define KK 32
#define ROW 68            // xyz, pad, 64 features
#define R2C 0.01f
#define GC 10
#define NCELL 1000
#define IMAX 0x7fffffff

// Transposed rows for grouping gather: [b][n][0..2]=xyz, [3]=pad, [4..67]=features
__device__ __align__(16) float g_t[(size_t)BB * NN * ROW];
// Grid-binned points: (x, y, z, index-as-float-bits)
__device__ __align__(16) float4 g_bpt[BB * NN];
__device__ int g_cnt[BB * NCELL];          // zero-init; re-zeroed by scan_kernel
__device__ int g_start[BB * (NCELL + 1)];
__device__ int g_rk[BB * NN];              // per-point: cell*16384 + within-cell rank

__device__ __forceinline__ int cell_of(float x) {
    int c = (int)(x * 10.0f);
    return c < 0 ? 0 : (c > 9 ? 9 : c);
}

// ---------------------------------------------------------------------------
// K1 (stream s1): pure transpose (B,3,N)+(B,C,N) -> (B,N,68) rows
// ---------------------------------------------------------------------------
__global__ void __launch_bounds__(256) transpose_kernel(
    const float* __restrict__ pc, const float* __restrict__ pf)
{
    __shared__ float tile[67][65];
    int b  = blockIdx.y;
    int n0 = blockIdx.x * 64;

    const float* src_c = pc + (size_t)b * 3 * NN;
    const float* src_f = pf + (size_t)b * CC * NN;

    // float4 loads along n
    for (int i = threadIdx.x; i < 67 * 16; i += 256) {
        int c = i >> 4, q = i & 15;
        const float* s = (c < 3) ? (src_c + (size_t)c * NN)
                                 : (src_f + (size_t)(c - 3) * NN);
        float4 v = *(const float4*)(s + n0 + q * 4);
        tile[c][q * 4 + 0] = v.x; tile[c][q * 4 + 1] = v.y;
        tile[c][q * 4 + 2] = v.z; tile[c][q * 4 + 3] = v.w;
    }
    __syncthreads();

    // float4 stores along the 68-float row (row = 272B, 16B aligned)
    float* dst = g_t + ((size_t)b * NN + n0) * ROW;
    for (int i = threadIdx.x; i < 64 * 17; i += 256) {
        int nl = i / 17, q = i % 17;
        float4 v;
        if (q == 0) { v.x = tile[0][nl]; v.y = tile[1][nl]; v.z = tile[2][nl]; v.w = 0.0f; }
        else { v.x = tile[4*q-1][nl]; v.y = tile[4*q][nl]; v.z = tile[4*q+1][nl]; v.w = tile[4*q+2][nl]; }
        *(float4*)(dst + (size_t)nl * ROW + q * 4) = v;
    }
}

// ---------------------------------------------------------------------------
// K2 (stream 0): histogram + within-cell rank
// ---------------------------------------------------------------------------
__global__ void __launch_bounds__(256) count_kernel(const float* __restrict__ pc)
{
    int t = blockIdx.x * 256 + threadIdx.x;
    if (t >= BB * NN) return;
    int b = t / NN, n = t % NN;
    const float* base = pc + (size_t)b * 3 * NN;
    float x = base[n], y = base[NN + n], z = base[2 * NN + n];
    int cell = (cell_of(x) * GC + cell_of(y)) * GC + cell_of(z);
    int rank = atomicAdd(&g_cnt[b * NCELL + cell], 1);
    g_rk[t] = cell * 16384 + rank;
}

// ---------------------------------------------------------------------------
// K3: exclusive scan per batch (1 block/batch); re-zeroes g_cnt for next run
// ---------------------------------------------------------------------------
__global__ void __launch_bounds__(1024) scan_kernel()
{
    __shared__ int s[NCELL];
    int b = blockIdx.x, t = threadIdx.x;
    int myc = 0;
    if (t < NCELL) {
        myc = g_cnt[b * NCELL + t];
        g_cnt[b * NCELL + t] = 0;      // restore invariant for next replay
        s[t] = myc;
    }
    __syncthreads();
    for (int off = 1; off < NCELL; off <<= 1) {
        int v = 0;
        if (t < NCELL && t >= off) v = s[t - off];
        __syncthreads();
        if (t < NCELL) s[t] += v;
        __syncthreads();
    }
    if (t < NCELL) g_start[b * (NCELL + 1) + t] = s[t] - myc;
    if (t == 0)    g_start[b * (NCELL + 1) + NCELL] = NN;
}

// ---------------------------------------------------------------------------
// K4: scatter points into bins — atomic-free (rank precomputed in K2)
// ---------------------------------------------------------------------------
__global__ void __launch_bounds__(256) scatter_kernel(const float* __restrict__ pc)
{
    int t = blockIdx.x * 256 + threadIdx.x;
    if (t >= BB * NN) return;
    int b = t / NN, n = t % NN;
    int rk   = g_rk[t];
    int cell = rk >> 14;
    int rank = rk & 16383;
    int pos  = g_start[b * (NCELL + 1) + cell] + rank;
    const float* base = pc + (size_t)b * 3 * NN;
    float x = base[n], y = base[NN + n], z = base[2 * NN + n];
    g_bpt[b * NN + pos] = make_float4(x, y, z, __int_as_float(n));
}

// ---------------------------------------------------------------------------
// Warp bitonic helpers (32 elems across lanes)
// ---------------------------------------------------------------------------
__device__ __forceinline__ void bstage(int& h, int lane, int j, int k)
{
    int o = __shfl_xor_sync(0xffffffffu, h, j);
    bool asc   = (lane & k) == 0;
    bool lower = (lane & j) == 0;
    h = (lower == asc) ? min(h, o) : max(h, o);
}
__device__ __forceinline__ void sort32(int& h, int lane)
{
    bstage(h, lane, 1, 2);
    bstage(h, lane, 2, 4);  bstage(h, lane, 1, 4);
    bstage(h, lane, 4, 8);  bstage(h, lane, 2, 8);  bstage(h, lane, 1, 8);
    bstage(h, lane, 8, 16); bstage(h, lane, 4, 16); bstage(h, lane, 2, 16); bstage(h, lane, 1, 16);
    bstage(h, lane, 16, 32); bstage(h, lane, 8, 32); bstage(h, lane, 4, 32);
    bstage(h, lane, 2, 32);  bstage(h, lane, 1, 32);
}
__device__ __forceinline__ void clean32(int& h, int lane)
{
    #pragma unroll
    for (int j = 16; j >= 1; j >>= 1) {
        int o = __shfl_xor_sync(0xffffffffu, h, j);
        h = ((lane & j) == 0) ? min(h, o) : max(h, o);
    }
}
__device__ __forceinline__ void merge_min32(int& a, int b, int lane)
{
    int br = __shfl_sync(0xffffffffu, b, 31 ^ lane);  // b reversed
    a = min(a, br);                                   // bitonic
    clean32(a, lane);
}

// ---------------------------------------------------------------------------
// K5: FUSED warp-per-center: grid ball query + adaptive top-32 + staged gather
//     smem 40KB/block; min 5 blocks/SM -> 40 warps/SM
// ---------------------------------------------------------------------------
__global__ void __launch_bounds__(256, 5) query_kernel(
    const float* __restrict__ cc, float* __restrict__ out)
{
    __shared__ int    hits[8][128];
    __shared__ float4 rows[8][32 * 9];     // 32 rows x 9 float4 per warp

    int wib  = threadIdx.x >> 5;
    int lane = threadIdx.x & 31;
    int* hb  = hits[wib];

    int gw = blockIdx.x * 8 + wib;
    int b = gw / MM;
    int m = gw % MM;

    const float* cb = cc + (size_t)b * 3 * MM;
    float cx = cb[m], cy = cb[MM + m], cz = cb[2 * MM + m];
    float c2 = __fadd_rn(__fadd_rn(__fmul_rn(cx, cx), __fmul_rn(cy, cy)),
                         __fmul_rn(cz, cz));

    int ci = cell_of(cx), cj = cell_of(cy), ck = cell_of(cz);
    int i0 = max(ci - 1, 0), i1 = min(ci + 1, 9);
    int j0 = max(cj - 1, 0), j1 = min(cj + 1, 9);
    int k0 = max(ck - 1, 0), k1 = min(ck + 1, 9);

    const float4* bpt = g_bpt + (size_t)b * NN;
    const int* st     = g_start + b * (NCELL + 1);

    unsigned below = (1u << lane) - 1u;
    int cnt = 0;

    // ---- search: 32 pts/step over the 3x3 cell-column ranges ----
    for (int i = i0; i <= i1; i++) {
        for (int j = j0; j <= j1; j++) {
            int cbase = (i * GC + j) * GC;
            int s = st[cbase + k0];
            int e = st[cbase + k1 + 1];     // k-range contiguous in bins
            for (int p0 = s; p0 < e; p0 += 32) {
                int p = p0 + lane;
                bool hit = false;
                float4 v;
                if (p < e) {
                    v = __ldg(bpt + p);
                    // reference p2: (x*x + y*y) + z*z, individually rounded
                    float p2 = __fadd_rn(__fadd_rn(__fmul_rn(v.x, v.x),
                                                   __fmul_rn(v.y, v.y)),
                                         __fmul_rn(v.z, v.z));
                    // reference inner: cuBLAS k=3 FMA chain
                    float inner = __fmaf_rn(cz, v.z,
                                  __fmaf_rn(cy, v.y, __fmul_rn(cx, v.x)));
                    float d2 = __fsub_rn(__fadd_rn(c2, p2),
                                         __fmul_rn(2.0f, inner));
                    hit = d2 < R2C;
                }
                unsigned wm = __ballot_sync(0xffffffffu, hit);
                if (hit) {
                    int rank = cnt + __popc(wm & below);
                    if (rank < 128) hb[rank] = __float_as_int(v.w);
                }
                cnt += __popc(wm);
            }
        }
    }
    __syncwarp();

    // ---- adaptive top-32 smallest (ascending) into h0; pads = IMAX ----
    int h0 = (lane < cnt) ? hb[lane] : IMAX;
    sort32(h0, lane);
    if (cnt > 32) {
        int h1 = (lane + 32 < cnt) ? hb[lane + 32] : IMAX;
        sort32(h1, lane);
        if (cnt > 64) {
            int h2 = (lane + 64 < cnt) ? hb[lane + 64] : IMAX;
            sort32(h2, lane);
            if (cnt > 96) {
                int h3 = (lane + 96 < cnt) ? hb[lane + 96] : IMAX;
                sort32(h3, lane);
                merge_min32(h2, h3, lane);
            }
            merge_min32(h0, h1, lane);
            merge_min32(h0, h2, lane);
        } else {
            merge_min32(h0, h1, lane);
        }
    }

    int myidx = h0;
    int first = __shfl_sync(0xffffffffu, h0, 0);
    if (first == IMAX) first = 0;
    if (myidx == IMAX) myidx = first;          // lane k = neighbor for slot k

    // ---- staged gather: 2 half-row passes through smem ----
    float4* rw = rows[wib];
    const float* tb = g_t + (size_t)b * NN * ROW;

    const unsigned CH = MM * KK;               // 65536
    unsigned ob = ((unsigned)(b * 67) * MM + m) * KK + lane;

    #pragma unroll
    for (int pass = 0; pass < 2; pass++) {
        // cooperative load: 32 rows x 9 float4 (pass0: q=0..8, pass1: q=8..16)
        #pragma unroll
        for (int it = 0; it < 9; it++) {
            int f  = it * 32 + lane;           // 0..287
            int r  = f / 9;
            int qq = f - r * 9;
            int idx = __shfl_sync(0xffffffffu, myidx, r);
            rw[f] = __ldg((const float4*)(tb + (unsigned)idx * ROW)
                          + pass * 8 + qq);
        }
        __syncwarp();

        // read-out: lane = k, stride 9 float4 (odd 16B stride: conflict-free)
        const float4* myrow = rw + lane * 9;
        if (pass == 0) {
            float4 v0 = myrow[0];              // xyz, pad
            out[ob]          = __fsub_rn(v0.x, cx);
            out[ob + CH]     = __fsub_rn(v0.y, cy);
            out[ob + 2 * CH] = __fsub_rn(v0.z, cz);
            #pragma unroll
            for (int qq = 1; qq < 9; qq++) {   // channels 3..34
                float4 v = myrow[qq];
                unsigned o = ob + (unsigned)(4 * qq - 1) * CH;
                out[o]          = v.x;
                out[o + CH]     = v.y;
                out[o + 2 * CH] = v.z;
                out[o + 3 * CH] = v.w;
            }
        } else {
            #pragma unroll
            for (int qq = 1; qq < 9; qq++) {   // channels 35..66
                float4 v = myrow[qq];
                unsigned o = ob + (unsigned)(4 * qq + 31) * CH;
                out[o]          = v.x;
                out[o + CH]     = v.y;
                out[o + 2 * CH] = v.z;
                out[o + 3 * CH] = v.w;
            }
        }
        __syncwarp();
    }
}

// ---------------------------------------------------------------------------
extern "C" void kernel_launch(void* const* d_in, const int* in_sizes, int n_in,
                              void* d_out, int out_size)
{
    const float* pc = (const float*)d_in[0];   // points_coords  (B,3,N)
    const float* cc = (const float*)d_in[1];   // centers_coords (B,3,M)
    const float* pf = (const float*)d_in[2];   // points_features(B,C,N)
    float* out = (float*)d_out;                // (B, 67, M, K)

    // lazy-init side stream + fork/join events (host objects only; graph
    // content is identical on every call)
    static cudaStream_t s1 = nullptr;
    static cudaEvent_t  e0 = nullptr, e1 = nullptr;
    if (!s1) {
        cudaStreamCreateWithFlags(&s1, cudaStreamNonBlocking);
        cudaEventCreateWithFlags(&e0, cudaEventDisableTiming);
        cudaEventCreateWithFlags(&e1, cudaEventDisableTiming);
    }

    // fork: transpose runs on s1, parallel to count->scan->scatter on stream 0
    cudaEventRecord(e0, 0);
    cudaStreamWaitEvent(s1, e0, 0);
    dim3 tgrid(NN / 64, BB);
    transpose_kernel<<<tgrid, 256, 0, s1>>>(pc, pf);
    cudaEventRecord(e1, s1);

    count_kernel<<<(BB * NN) / 256, 256>>>(pc);
    scan_kernel<<<BB, 1024>>>();
    scatter_kernel<<<(BB * NN) / 256, 256>>>(pc);

    // join: fused query needs g_t (s1) and g_bpt/g_start (stream 0)
    cudaStreamWaitEvent(0, e1, 0);
    query_kernel<<<BB * MM / 8, 256>>>(cc, out);
}

// round 11
// speedup vs baseline: 1.0261x; 1.0261x over previous
#include <cuda_runtime.h>

#define BB 4
#define NN 16384
#define MM 2048
#define CC 64
#define KK 32
#define ROW 68            // xyz, pad, 64 features
#define R2C 0.01f
#define R2P 0.01001f      // prune threshold: R2C + safety margin
#define GC 10
#define NCELL 1000
#define IMAX 0x7fffffff

// Transposed rows for grouping gather: [b][n][0..2]=xyz, [3]=pad, [4..67]=features
__device__ __align__(16) float g_t[(size_t)BB * NN * ROW];
// Grid-binned points: (x, y, z, index-as-float-bits)
__device__ __align__(16) float4 g_bpt[BB * NN];
__device__ int g_cnt[BB * NCELL];          // zero-init; re-zeroed by scan_kernel
__device__ int g_start[BB * (NCELL + 1)];
__device__ int g_rk[BB * NN];              // per-point: cell*16384 + within-cell rank

__device__ __forceinline__ int cell_of(float x) {
    int c = (int)(x * 10.0f);
    return c < 0 ? 0 : (c > 9 ? 9 : c);
}

// ---------------------------------------------------------------------------
// K1 (stream s1): pure transpose (B,3,N)+(B,C,N) -> (B,N,68) rows
// ---------------------------------------------------------------------------
__global__ void __launch_bounds__(256) transpose_kernel(
    const float* __restrict__ pc, const float* __restrict__ pf)
{
    __shared__ float tile[67][65];
    int b  = blockIdx.y;
    int n0 = blockIdx.x * 64;

    const float* src_c = pc + (size_t)b * 3 * NN;
    const float* src_f = pf + (size_t)b * CC * NN;

    // float4 loads along n
    for (int i = threadIdx.x; i < 67 * 16; i += 256) {
        int c = i >> 4, q = i & 15;
        const float* s = (c < 3) ? (src_c + (size_t)c * NN)
                                 : (src_f + (size_t)(c - 3) * NN);
        float4 v = *(const float4*)(s + n0 + q * 4);
        tile[c][q * 4 + 0] = v.x; tile[c][q * 4 + 1] = v.y;
        tile[c][q * 4 + 2] = v.z; tile[c][q * 4 + 3] = v.w;
    }
    __syncthreads();

    // float4 stores along the 68-float row (row = 272B, 16B aligned)
    float* dst = g_t + ((size_t)b * NN + n0) * ROW;
    for (int i = threadIdx.x; i < 64 * 17; i += 256) {
        int nl = i / 17, q = i % 17;
        float4 v;
        if (q == 0) { v.x = tile[0][nl]; v.y = tile[1][nl]; v.z = tile[2][nl]; v.w = 0.0f; }
        else { v.x = tile[4*q-1][nl]; v.y = tile[4*q][nl]; v.z = tile[4*q+1][nl]; v.w = tile[4*q+2][nl]; }
        *(float4*)(dst + (size_t)nl * ROW + q * 4) = v;
    }
}

// ---------------------------------------------------------------------------
// K2 (stream 0): histogram + within-cell rank
// ---------------------------------------------------------------------------
__global__ void __launch_bounds__(256) count_kernel(const float* __restrict__ pc)
{
    int t = blockIdx.x * 256 + threadIdx.x;
    if (t >= BB * NN) return;
    int b = t / NN, n = t % NN;
    const float* base = pc + (size_t)b * 3 * NN;
    float x = base[n], y = base[NN + n], z = base[2 * NN + n];
    int cell = (cell_of(x) * GC + cell_of(y)) * GC + cell_of(z);
    int rank = atomicAdd(&g_cnt[b * NCELL + cell], 1);
    g_rk[t] = cell * 16384 + rank;
}

// ---------------------------------------------------------------------------
// K3: exclusive scan per batch (1 block/batch); re-zeroes g_cnt for next run
// ---------------------------------------------------------------------------
__global__ void __launch_bounds__(1024) scan_kernel()
{
    __shared__ int s[NCELL];
    int b = blockIdx.x, t = threadIdx.x;
    int myc = 0;
    if (t < NCELL) {
        myc = g_cnt[b * NCELL + t];
        g_cnt[b * NCELL + t] = 0;      // restore invariant for next replay
        s[t] = myc;
    }
    __syncthreads();
    for (int off = 1; off < NCELL; off <<= 1) {
        int v = 0;
        if (t < NCELL && t >= off) v = s[t - off];
        __syncthreads();
        if (t < NCELL) s[t] += v;
        __syncthreads();
    }
    if (t < NCELL) g_start[b * (NCELL + 1) + t] = s[t] - myc;
    if (t == 0)    g_start[b * (NCELL + 1) + NCELL] = NN;
}

// ---------------------------------------------------------------------------
// K4: scatter points into bins — atomic-free (rank precomputed in K2)
// ---------------------------------------------------------------------------
__global__ void __launch_bounds__(256) scatter_kernel(const float* __restrict__ pc)
{
    int t = blockIdx.x * 256 + threadIdx.x;
    if (t >= BB * NN) return;
    int b = t / NN, n = t % NN;
    int rk   = g_rk[t];
    int cell = rk >> 14;
    int rank = rk & 16383;
    int pos  = g_start[b * (NCELL + 1) + cell] + rank;
    const float* base = pc + (size_t)b * 3 * NN;
    float x = base[n], y = base[NN + n], z = base[2 * NN + n];
    g_bpt[b * NN + pos] = make_float4(x, y, z, __int_as_float(n));
}

// ---------------------------------------------------------------------------
// Warp bitonic helpers (32 elems across lanes)
// ---------------------------------------------------------------------------
__device__ __forceinline__ void bstage(int& h, int lane, int j, int k)
{
    int o = __shfl_xor_sync(0xffffffffu, h, j);
    bool asc   = (lane & k) == 0;
    bool lower = (lane & j) == 0;
    h = (lower == asc) ? min(h, o) : max(h, o);
}
__device__ __forceinline__ void sort32(int& h, int lane)
{
    bstage(h, lane, 1, 2);
    bstage(h, lane, 2, 4);  bstage(h, lane, 1, 4);
    bstage(h, lane, 4, 8);  bstage(h, lane, 2, 8);  bstage(h, lane, 1, 8);
    bstage(h, lane, 8, 16); bstage(h, lane, 4, 16); bstage(h, lane, 2, 16); bstage(h, lane, 1, 16);
    bstage(h, lane, 16, 32); bstage(h, lane, 8, 32); bstage(h, lane, 4, 32);
    bstage(h, lane, 2, 32);  bstage(h, lane, 1, 32);
}
__device__ __forceinline__ void clean32(int& h, int lane)
{
    #pragma unroll
    for (int j = 16; j >= 1; j >>= 1) {
        int o = __shfl_xor_sync(0xffffffffu, h, j);
        h = ((lane & j) == 0) ? min(h, o) : max(h, o);
    }
}
__device__ __forceinline__ void merge_min32(int& a, int b, int lane)
{
    int br = __shfl_sync(0xffffffffu, b, 31 ^ lane);  // b reversed
    a = min(a, br);                                   // bitonic
    clean32(a, lane);
}

// ---------------------------------------------------------------------------
// K5: FUSED warp-per-center: grid ball query (z-pruned) + adaptive top-32 +
//     direct batched gather (R5 structure — best measured)
// ---------------------------------------------------------------------------
__global__ void __launch_bounds__(256, 4) query_kernel(
    const float* __restrict__ cc, float* __restrict__ out)
{
    __shared__ int hits[8][128];
    int wib  = threadIdx.x >> 5;
    int lane = threadIdx.x & 31;
    int* hb  = hits[wib];

    int gw = blockIdx.x * 8 + wib;
    int b = gw / MM;
    int m = gw % MM;

    const float* cb = cc + (size_t)b * 3 * MM;
    float cx = cb[m], cy = cb[MM + m], cz = cb[2 * MM + m];
    float c2 = __fadd_rn(__fadd_rn(__fmul_rn(cx, cx), __fmul_rn(cy, cy)),
                         __fmul_rn(cz, cz));

    int ci = cell_of(cx), cj = cell_of(cy), ck = cell_of(cz);
    int i0 = max(ci - 1, 0), i1 = min(ci + 1, 9);
    int j0 = max(cj - 1, 0), j1 = min(cj + 1, 9);
    int k0 = max(ck - 1, 0), k1 = min(ck + 1, 9);

    const float4* bpt = g_bpt + (size_t)b * NN;
    const int* st     = g_start + b * (NCELL + 1);

    unsigned below = (1u << lane) - 1u;
    int cnt = 0;

    for (int i = i0; i <= i1; i++) {
        // conservative min |dx| from center to cell-i x-range
        float dx = 0.0f;
        if (i < ci)      dx = fmaxf(cx - (i + 1) * 0.1f, 0.0f);
        else if (i > ci) dx = fmaxf(i * 0.1f - cx, 0.0f);
        for (int j = j0; j <= j1; j++) {
            float dy = 0.0f;
            if (j < cj)      dy = fmaxf(cy - (j + 1) * 0.1f, 0.0f);
            else if (j > cj) dy = fmaxf(j * 0.1f - cy, 0.0f);
            float d2xy = dx * dx + dy * dy;
            if (d2xy >= R2P) continue;                    // column unreachable
            // reachable z-window (inflated: cannot drop a reference hit)
            float dzm = sqrtf(R2P - d2xy) + 2e-5f;
            int kk0 = max(k0, (int)floorf((cz - dzm) * 10.0f));
            int kk1 = min(k1, (int)floorf((cz + dzm) * 10.0f));
            if (kk1 < kk0) continue;

            int cbase = (i * GC + j) * GC;
            int s = st[cbase + kk0];
            int e = st[cbase + kk1 + 1];    // k-range contiguous in bins
            for (int p0 = s; p0 < e; p0 += 32) {
                int p = p0 + lane;
                bool hit = false;
                float4 v;
                if (p < e) {
                    v = __ldg(bpt + p);
                    // reference p2: (x*x + y*y) + z*z, individually rounded
                    float p2 = __fadd_rn(__fadd_rn(__fmul_rn(v.x, v.x),
                                                   __fmul_rn(v.y, v.y)),
                                         __fmul_rn(v.z, v.z));
                    // reference inner: cuBLAS k=3 FMA chain
                    float inner = __fmaf_rn(cz, v.z,
                                  __fmaf_rn(cy, v.y, __fmul_rn(cx, v.x)));
                    float d2 = __fsub_rn(__fadd_rn(c2, p2),
                                         __fmul_rn(2.0f, inner));
                    hit = d2 < R2C;
                }
                unsigned wm = __ballot_sync(0xffffffffu, hit);
                if (hit) {
                    int rank = cnt + __popc(wm & below);
                    if (rank < 128) hb[rank] = __float_as_int(v.w);
                }
                cnt += __popc(wm);
            }
        }
    }
    __syncwarp();

    // ---- adaptive top-32 smallest (ascending) into h0; pads = IMAX ----
    int h0 = (lane < cnt) ? hb[lane] : IMAX;
    sort32(h0, lane);
    if (cnt > 32) {
        int h1 = (lane + 32 < cnt) ? hb[lane + 32] : IMAX;
        sort32(h1, lane);
        if (cnt > 64) {
            int h2 = (lane + 64 < cnt) ? hb[lane + 64] : IMAX;
            sort32(h2, lane);
            if (cnt > 96) {
                int h3 = (lane + 96 < cnt) ? hb[lane + 96] : IMAX;
                sort32(h3, lane);
                merge_min32(h2, h3, lane);
            }
            merge_min32(h0, h1, lane);
            merge_min32(h0, h2, lane);
        } else {
            merge_min32(h0, h1, lane);
        }
    }

    int myidx = h0;
    int first = __shfl_sync(0xffffffffu, h0, 0);
    if (first == IMAX) first = 0;
    if (myidx == IMAX) myidx = first;          // lane k = neighbor for slot k

    // ---- direct gather: lane = output slot k; batched loads for MLP ----
    const float4* r4 = (const float4*)(g_t + ((size_t)b * NN + myidx) * ROW);

    const size_t CH = (size_t)MM * KK;
    size_t ob = (((size_t)b * 67) * MM + m) * KK + lane;

    {
        float4 w[9];
        #pragma unroll
        for (int q = 0; q < 9; q++) w[q] = __ldg(r4 + q);   // w[0] = xyz,pad
        out[ob]          = __fsub_rn(w[0].x, cx);
        out[ob + CH]     = __fsub_rn(w[0].y, cy);
        out[ob + 2 * CH] = __fsub_rn(w[0].z, cz);
        #pragma unroll
        for (int q = 1; q < 9; q++) {
            size_t o = ob + (size_t)(4 * q - 1) * CH;       // channels 4q-1..4q+2
            out[o]          = w[q].x;
            out[o + CH]     = w[q].y;
            out[o + 2 * CH] = w[q].z;
            out[o + 3 * CH] = w[q].w;
        }
    }
    {
        float4 u[8];
        #pragma unroll
        for (int q = 0; q < 8; q++) u[q] = __ldg(r4 + 9 + q);
        #pragma unroll
        for (int q = 0; q < 8; q++) {
            size_t o = ob + (size_t)(35 + 4 * q) * CH;      // channels 35..66
            out[o]          = u[q].x;
            out[o + CH]     = u[q].y;
            out[o + 2 * CH] = u[q].z;
            out[o + 3 * CH] = u[q].w;
        }
    }
}

// ---------------------------------------------------------------------------
extern "C" void kernel_launch(void* const* d_in, const int* in_sizes, int n_in,
                              void* d_out, int out_size)
{
    const float* pc = (const float*)d_in[0];   // points_coords  (B,3,N)
    const float* cc = (const float*)d_in[1];   // centers_coords (B,3,M)
    const float* pf = (const float*)d_in[2];   // points_features(B,C,N)
    float* out = (float*)d_out;                // (B, 67, M, K)

    // lazy-init side stream + fork/join events (host objects only; graph
    // content is identical on every call)
    static cudaStream_t s1 = nullptr;
    static cudaEvent_t  e0 = nullptr, e1 = nullptr;
    if (!s1) {
        cudaStreamCreateWithFlags(&s1, cudaStreamNonBlocking);
        cudaEventCreateWithFlags(&e0, cudaEventDisableTiming);
        cudaEventCreateWithFlags(&e1, cudaEventDisableTiming);
    }

    // fork: transpose runs on s1, parallel to count->scan->scatter on stream 0
    cudaEventRecord(e0, 0);
    cudaStreamWaitEvent(s1, e0, 0);
    dim3 tgrid(NN / 64, BB);
    transpose_kernel<<<tgrid, 256, 0, s1>>>(pc, pf);
    cudaEventRecord(e1, s1);

    count_kernel<<<(BB * NN) / 256, 256>>>(pc);
    scan_kernel<<<BB, 1024>>>();
    scatter_kernel<<<(BB * NN) / 256, 256>>>(pc);

    // join: fused query needs g_t (s1) and g_bpt/g_start (stream 0)
    cudaStreamWaitEvent(0, e1, 0);
    query_kernel<<<BB * MM / 8, 256>>>(cc, out);
}

// round 12
// speedup vs baseline: 1.1382x; 1.1093x over previous
#include <cuda_runtime.h>

#define BB 4
#define NN 16384
#define MM 2048
#define CC 64
#define KK 32
#define ROW 68            // xyz, pad, 64 features
#define R2C 0.01f
#define GC 10
#define NCELL 1000
#define IMAX 0x7fffffff

// Transposed rows for grouping gather: [b][n][0..2]=xyz, [3]=pad, [4..67]=features
__device__ __align__(16) float g_t[(size_t)BB * NN * ROW];
// Grid-binned points: (x, y, z, index-as-float-bits)
__device__ __align__(16) float4 g_bpt[BB * NN];
__device__ int g_cnt[BB * NCELL];          // zero-init; re-zeroed by scan_kernel
__device__ int g_start[BB * (NCELL + 1)];
__device__ int g_rk[BB * NN];              // per-point: cell*16384 + within-cell rank

__device__ __forceinline__ int cell_of(float x) {
    int c = (int)(x * 10.0f);
    return c < 0 ? 0 : (c > 9 ? 9 : c);
}

// ---------------------------------------------------------------------------
// K1: transpose (B,3,N)+(B,C,N) -> (B,N,68) rows; fused histogram + rank
// ---------------------------------------------------------------------------
__global__ void __launch_bounds__(256) transpose_kernel(
    const float* __restrict__ pc, const float* __restrict__ pf)
{
    __shared__ float tile[67][65];
    int b  = blockIdx.y;
    int n0 = blockIdx.x * 64;

    const float* src_c = pc + (size_t)b * 3 * NN;
    const float* src_f = pf + (size_t)b * CC * NN;

    // float4 loads along n
    for (int i = threadIdx.x; i < 67 * 16; i += 256) {
        int c = i >> 4, q = i & 15;
        const float* s = (c < 3) ? (src_c + (size_t)c * NN)
                                 : (src_f + (size_t)(c - 3) * NN);
        float4 v = *(const float4*)(s + n0 + q * 4);
        tile[c][q * 4 + 0] = v.x; tile[c][q * 4 + 1] = v.y;
        tile[c][q * 4 + 2] = v.z; tile[c][q * 4 + 3] = v.w;
    }
    __syncthreads();

    // fused histogram: atomic returns within-cell rank; save cell+rank per point
    if (threadIdx.x < 64) {
        int t = threadIdx.x;
        float x = tile[0][t], y = tile[1][t], z = tile[2][t];
        int cell = (cell_of(x) * GC + cell_of(y)) * GC + cell_of(z);
        int rank = atomicAdd(&g_cnt[b * NCELL + cell], 1);
        g_rk[b * NN + n0 + t] = cell * 16384 + rank;
    }

    // float4 stores along the 68-float row (row = 272B, 16B aligned)
    float* dst = g_t + ((size_t)b * NN + n0) * ROW;
    for (int i = threadIdx.x; i < 64 * 17; i += 256) {
        int nl = i / 17, q = i % 17;
        float4 v;
        if (q == 0) { v.x = tile[0][nl]; v.y = tile[1][nl]; v.z = tile[2][nl]; v.w = 0.0f; }
        else { v.x = tile[4*q-1][nl]; v.y = tile[4*q][nl]; v.z = tile[4*q+1][nl]; v.w = tile[4*q+2][nl]; }
        *(float4*)(dst + (size_t)nl * ROW + q * 4) = v;
    }
}

// ---------------------------------------------------------------------------
// K2: exclusive scan per batch (1 block/batch); re-zeroes g_cnt for next run
// ---------------------------------------------------------------------------
__global__ void __launch_bounds__(1024) scan_kernel()
{
    __shared__ int s[NCELL];
    int b = blockIdx.x, t = threadIdx.x;
    int myc = 0;
    if (t < NCELL) {
        myc = g_cnt[b * NCELL + t];
        g_cnt[b * NCELL + t] = 0;      // restore invariant for next replay
        s[t] = myc;
    }
    __syncthreads();
    for (int off = 1; off < NCELL; off <<= 1) {
        int v = 0;
        if (t < NCELL && t >= off) v = s[t - off];
        __syncthreads();
        if (t < NCELL) s[t] += v;
        __syncthreads();
    }
    if (t < NCELL) g_start[b * (NCELL + 1) + t] = s[t] - myc;
    if (t == 0)    g_start[b * (NCELL + 1) + NCELL] = NN;
}

// ---------------------------------------------------------------------------
// K3: scatter points into bins — atomic-free (rank precomputed in K1)
// ---------------------------------------------------------------------------
__global__ void __launch_bounds__(256) scatter_kernel(const float* __restrict__ pc)
{
    int t = blockIdx.x * 256 + threadIdx.x;
    if (t >= BB * NN) return;
    int b = t / NN, n = t % NN;
    int rk   = g_rk[t];
    int cell = rk >> 14;
    int rank = rk & 16383;
    int pos  = g_start[b * (NCELL + 1) + cell] + rank;
    const float* base = pc + (size_t)b * 3 * NN;
    float x = base[n], y = base[NN + n], z = base[2 * NN + n];
    g_bpt[b * NN + pos] = make_float4(x, y, z, __int_as_float(n));
}

// ---------------------------------------------------------------------------
// Warp bitonic helpers (32 elems across lanes)
// ---------------------------------------------------------------------------
__device__ __forceinline__ void bstage(int& h, int lane, int j, int k)
{
    int o = __shfl_xor_sync(0xffffffffu, h, j);
    bool asc   = (lane & k) == 0;
    bool lower = (lane & j) == 0;
    h = (lower == asc) ? min(h, o) : max(h, o);
}
__device__ __forceinline__ void sort32(int& h, int lane)
{
    bstage(h, lane, 1, 2);
    bstage(h, lane, 2, 4);  bstage(h, lane, 1, 4);
    bstage(h, lane, 4, 8);  bstage(h, lane, 2, 8);  bstage(h, lane, 1, 8);
    bstage(h, lane, 8, 16); bstage(h, lane, 4, 16); bstage(h, lane, 2, 16); bstage(h, lane, 1, 16);
    bstage(h, lane, 16, 32); bstage(h, lane, 8, 32); bstage(h, lane, 4, 32);
    bstage(h, lane, 2, 32);  bstage(h, lane, 1, 32);
}
__device__ __forceinline__ void clean32(int& h, int lane)
{
    #pragma unroll
    for (int j = 16; j >= 1; j >>= 1) {
        int o = __shfl_xor_sync(0xffffffffu, h, j);
        h = ((lane & j) == 0) ? min(h, o) : max(h, o);
    }
}
__device__ __forceinline__ void merge_min32(int& a, int b, int lane)
{
    int br = __shfl_sync(0xffffffffu, b, 31 ^ lane);  // b reversed
    a = min(a, br);                                   // bitonic
    clean32(a, lane);
}

// ---------------------------------------------------------------------------
// K4: FUSED warp-per-center (R5 structure, measured best):
//     grid ball query + ADAPTIVE top-32 select + direct batched gather
// ---------------------------------------------------------------------------
__global__ void __launch_bounds__(256, 4) query_kernel(
    const float* __restrict__ cc, float* __restrict__ out)
{
    __shared__ int hits[8][128];
    int wib  = threadIdx.x >> 5;
    int lane = threadIdx.x & 31;
    int* hb  = hits[wib];

    int gw = blockIdx.x * 8 + wib;
    int b = gw / MM;
    int m = gw % MM;

    const float* cb = cc + (size_t)b * 3 * MM;
    float cx = cb[m], cy = cb[MM + m], cz = cb[2 * MM + m];
    float c2 = __fadd_rn(__fadd_rn(__fmul_rn(cx, cx), __fmul_rn(cy, cy)),
                         __fmul_rn(cz, cz));

    int ci = cell_of(cx), cj = cell_of(cy), ck = cell_of(cz);
    int i0 = max(ci - 1, 0), i1 = min(ci + 1, 9);
    int j0 = max(cj - 1, 0), j1 = min(cj + 1, 9);
    int k0 = max(ck - 1, 0), k1 = min(ck + 1, 9);

    const float4* bpt = g_bpt + (size_t)b * NN;
    const int* st     = g_start + b * (NCELL + 1);

    unsigned below = (1u << lane) - 1u;
    int cnt = 0;

    for (int i = i0; i <= i1; i++) {
        for (int j = j0; j <= j1; j++) {
            int cbase = (i * GC + j) * GC;
            int s = st[cbase + k0];
            int e = st[cbase + k1 + 1];     // k-range contiguous in bins
            for (int p0 = s; p0 < e; p0 += 32) {
                int p = p0 + lane;
                bool hit = false;
                float4 v;
                if (p < e) {
                    v = __ldg(bpt + p);
                    // reference p2: (x*x + y*y) + z*z, individually rounded
                    float p2 = __fadd_rn(__fadd_rn(__fmul_rn(v.x, v.x),
                                                   __fmul_rn(v.y, v.y)),
                                         __fmul_rn(v.z, v.z));
                    // reference inner: cuBLAS k=3 FMA chain
                    float inner = __fmaf_rn(cz, v.z,
                                  __fmaf_rn(cy, v.y, __fmul_rn(cx, v.x)));
                    float d2 = __fsub_rn(__fadd_rn(c2, p2),
                                         __fmul_rn(2.0f, inner));
                    hit = d2 < R2C;
                }
                unsigned wm = __ballot_sync(0xffffffffu, hit);
                if (hit) {
                    int rank = cnt + __popc(wm & below);
                    if (rank < 128) hb[rank] = __float_as_int(v.w);
                }
                cnt += __popc(wm);
            }
        }
    }
    __syncwarp();

    // ---- ADAPTIVE top-32 smallest (ascending) into h0; pads = IMAX ----
    int h0 = (lane < cnt) ? hb[lane] : IMAX;
    sort32(h0, lane);
    if (cnt > 32) {
        int h1 = (lane + 32 < cnt) ? hb[lane + 32] : IMAX;
        sort32(h1, lane);
        if (cnt > 64) {
            int h2 = (lane + 64 < cnt) ? hb[lane + 64] : IMAX;
            sort32(h2, lane);
            if (cnt > 96) {
                int h3 = (lane + 96 < cnt) ? hb[lane + 96] : IMAX;
                sort32(h3, lane);
                merge_min32(h2, h3, lane);
            }
            merge_min32(h0, h1, lane);
            merge_min32(h0, h2, lane);
        } else {
            merge_min32(h0, h1, lane);
        }
    }

    int myidx = h0;
    int first = __shfl_sync(0xffffffffu, h0, 0);
    if (first == IMAX) first = 0;
    if (myidx == IMAX) myidx = first;          // lane k = neighbor for slot k

    // ---- direct gather: lane = output slot k; batched loads for MLP ----
    const float4* r4 = (const float4*)(g_t + ((size_t)b * NN + myidx) * ROW);

    const size_t CH = (size_t)MM * KK;
    size_t ob = (((size_t)b * 67) * MM + m) * KK + lane;

    {
        float4 w[9];
        #pragma unroll
        for (int q = 0; q < 9; q++) w[q] = __ldg(r4 + q);   // w[0] = xyz,pad
        out[ob]          = __fsub_rn(w[0].x, cx);
        out[ob + CH]     = __fsub_rn(w[0].y, cy);
        out[ob + 2 * CH] = __fsub_rn(w[0].z, cz);
        #pragma unroll
        for (int q = 1; q < 9; q++) {
            size_t o = ob + (size_t)(4 * q - 1) * CH;       // channels 4q-1..4q+2
            out[o]          = w[q].x;
            out[o + CH]     = w[q].y;
            out[o + 2 * CH] = w[q].z;
            out[o + 3 * CH] = w[q].w;
        }
    }
    {
        float4 u[8];
        #pragma unroll
        for (int q = 0; q < 8; q++) u[q] = __ldg(r4 + 9 + q);
        #pragma unroll
        for (int q = 0; q < 8; q++) {
            size_t o = ob + (size_t)(35 + 4 * q) * CH;      // channels 35..66
            out[o]          = u[q].x;
            out[o + CH]     = u[q].y;
            out[o + 2 * CH] = u[q].z;
            out[o + 3 * CH] = u[q].w;
        }
    }
}

// ---------------------------------------------------------------------------
extern "C" void kernel_launch(void* const* d_in, const int* in_sizes, int n_in,
                              void* d_out, int out_size)
{
    const float* pc = (const float*)d_in[0];   // points_coords  (B,3,N)
    const float* cc = (const float*)d_in[1];   // centers_coords (B,3,M)
    const float* pf = (const float*)d_in[2];   // points_features(B,C,N)
    float* out = (float*)d_out;                // (B, 67, M, K)

    dim3 tgrid(NN / 64, BB);
    transpose_kernel<<<tgrid, 256>>>(pc, pf);
    scan_kernel<<<BB, 1024>>>();
    scatter_kernel<<<(BB * NN) / 256, 256>>>(pc);
    query_kernel<<<BB * MM / 8, 256>>>(cc, out);
}

// round 14
// speedup vs baseline: 1.1620x; 1.0208x over previous
#include <cuda_runtime.h>

#define BB 4
#define NN 16384
#define MM 2048
#define CC 64
#define KK 32
#define ROW 68            // xyz, pad, 64 features
#define R2C 0.01f
#define R2P 0.01001f      // prune threshold: R2C + safety margin
#define GC 10
#define NCELL 1000
#define IMAX 0x7fffffff

// Transposed rows for grouping gather: [b][n][0..2]=xyz, [3]=pad, [4..67]=features
__device__ __align__(16) float g_t[(size_t)BB * NN * ROW];
// Grid-binned points: (x, y, z, index-as-float-bits)
__device__ __align__(16) float4 g_bpt[BB * NN];
__device__ int g_cnt[BB * NCELL];          // zero-init; re-zeroed by scan_kernel
__device__ int g_start[BB * (NCELL + 1)];
__device__ int g_rk[BB * NN];              // per-point: cell*16384 + within-cell rank

__device__ __forceinline__ int cell_of(float x) {
    int c = (int)(x * 10.0f);
    return c < 0 ? 0 : (c > 9 ? 9 : c);
}

// ---------------------------------------------------------------------------
// K1: transpose (B,3,N)+(B,C,N) -> (B,N,68) rows; fused histogram + rank
// ---------------------------------------------------------------------------
__global__ void __launch_bounds__(256) transpose_kernel(
    const float* __restrict__ pc, const float* __restrict__ pf)
{
    __shared__ float tile[67][65];
    int b  = blockIdx.y;
    int n0 = blockIdx.x * 64;

    const float* src_c = pc + (size_t)b * 3 * NN;
    const float* src_f = pf + (size_t)b * CC * NN;

    // float4 loads along n
    for (int i = threadIdx.x; i < 67 * 16; i += 256) {
        int c = i >> 4, q = i & 15;
        const float* s = (c < 3) ? (src_c + (size_t)c * NN)
                                 : (src_f + (size_t)(c - 3) * NN);
        float4 v = *(const float4*)(s + n0 + q * 4);
        tile[c][q * 4 + 0] = v.x; tile[c][q * 4 + 1] = v.y;
        tile[c][q * 4 + 2] = v.z; tile[c][q * 4 + 3] = v.w;
    }
    __syncthreads();

    // fused histogram: atomic returns within-cell rank; save cell+rank per point
    if (threadIdx.x < 64) {
        int t = threadIdx.x;
        float x = tile[0][t], y = tile[1][t], z = tile[2][t];
        int cell = (cell_of(x) * GC + cell_of(y)) * GC + cell_of(z);
        int rank = atomicAdd(&g_cnt[b * NCELL + cell], 1);
        g_rk[b * NN + n0 + t] = cell * 16384 + rank;
    }

    // float4 stores along the 68-float row (row = 272B, 16B aligned)
    float* dst = g_t + ((size_t)b * NN + n0) * ROW;
    for (int i = threadIdx.x; i < 64 * 17; i += 256) {
        int nl = i / 17, q = i % 17;
        float4 v;
        if (q == 0) { v.x = tile[0][nl]; v.y = tile[1][nl]; v.z = tile[2][nl]; v.w = 0.0f; }
        else { v.x = tile[4*q-1][nl]; v.y = tile[4*q][nl]; v.z = tile[4*q+1][nl]; v.w = tile[4*q+2][nl]; }
        *(float4*)(dst + (size_t)nl * ROW + q * 4) = v;
    }
}

// ---------------------------------------------------------------------------
// K2: exclusive scan per batch (1 block/batch); re-zeroes g_cnt for next run
// ---------------------------------------------------------------------------
__global__ void __launch_bounds__(1024) scan_kernel()
{
    __shared__ int s[NCELL];
    int b = blockIdx.x, t = threadIdx.x;
    int myc = 0;
    if (t < NCELL) {
        myc = g_cnt[b * NCELL + t];
        g_cnt[b * NCELL + t] = 0;      // restore invariant for next replay
        s[t] = myc;
    }
    __syncthreads();
    for (int off = 1; off < NCELL; off <<= 1) {
        int v = 0;
        if (t < NCELL && t >= off) v = s[t - off];
        __syncthreads();
        if (t < NCELL) s[t] += v;
        __syncthreads();
    }
    if (t < NCELL) g_start[b * (NCELL + 1) + t] = s[t] - myc;
    if (t == 0)    g_start[b * (NCELL + 1) + NCELL] = NN;
}

// ---------------------------------------------------------------------------
// K3: scatter — atomic-free, 4 points/thread with front-batched loads (ILP)
// ---------------------------------------------------------------------------
__global__ void __launch_bounds__(256) scatter_kernel(const float* __restrict__ pc)
{
    int t = blockIdx.x * 256 + threadIdx.x;    // 0..16383
    // 4 independent points: p = t + i*16384 ; b = p>>14, n = p&16383
    int   rk[4];
    float x[4], y[4], z[4];
    #pragma unroll
    for (int i = 0; i < 4; i++) {
        int p = t + i * 16384;
        rk[i] = __ldg(g_rk + p);
        int b = p >> 14, n = p & 16383;
        const float* base = pc + (size_t)b * 3 * NN;
        x[i] = __ldg(base + n);
        y[i] = __ldg(base + NN + n);
        z[i] = __ldg(base + 2 * NN + n);
    }
    #pragma unroll
    for (int i = 0; i < 4; i++) {
        int p = t + i * 16384;
        int b = p >> 14, n = p & 16383;
        int cell = rk[i] >> 14;
        int rank = rk[i] & 16383;
        int pos  = __ldg(g_start + b * (NCELL + 1) + cell) + rank;
        g_bpt[b * NN + pos] = make_float4(x[i], y[i], z[i], __int_as_float(n));
    }
}

// ---------------------------------------------------------------------------
// Warp bitonic helpers (32 elems across lanes)
// ---------------------------------------------------------------------------
__device__ __forceinline__ void bstage(int& h, int lane, int j, int k)
{
    int o = __shfl_xor_sync(0xffffffffu, h, j);
    bool asc   = (lane & k) == 0;
    bool lower = (lane & j) == 0;
    h = (lower == asc) ? min(h, o) : max(h, o);
}
__device__ __forceinline__ void sort32(int& h, int lane)
{
    bstage(h, lane, 1, 2);
    bstage(h, lane, 2, 4);  bstage(h, lane, 1, 4);
    bstage(h, lane, 4, 8);  bstage(h, lane, 2, 8);  bstage(h, lane, 1, 8);
    bstage(h, lane, 8, 16); bstage(h, lane, 4, 16); bstage(h, lane, 2, 16); bstage(h, lane, 1, 16);
    bstage(h, lane, 16, 32); bstage(h, lane, 8, 32); bstage(h, lane, 4, 32);
    bstage(h, lane, 2, 32);  bstage(h, lane, 1, 32);
}
__device__ __forceinline__ void clean32(int& h, int lane)
{
    #pragma unroll
    for (int j = 16; j >= 1; j >>= 1) {
        int o = __shfl_xor_sync(0xffffffffu, h, j);
        h = ((lane & j) == 0) ? min(h, o) : max(h, o);
    }
}
__device__ __forceinline__ void merge_min32(int& a, int b, int lane)
{
    int br = __shfl_sync(0xffffffffu, b, 31 ^ lane);  // b reversed
    a = min(a, br);                                   // bitonic
    clean32(a, lane);
}

// ---------------------------------------------------------------------------
// K4: FUSED warp-per-center: grid ball query (z-window pruned) +
//     adaptive top-32 select + direct batched gather
// ---------------------------------------------------------------------------
__global__ void __launch_bounds__(256, 4) query_kernel(
    const float* __restrict__ cc, float* __restrict__ out)
{
    __shared__ int hits[8][128];
    int wib  = threadIdx.x >> 5;
    int lane = threadIdx.x & 31;
    int* hb  = hits[wib];

    int gw = blockIdx.x * 8 + wib;
    int b = gw / MM;
    int m = gw % MM;

    const float* cb = cc + (size_t)b * 3 * MM;
    float cx = cb[m], cy = cb[MM + m], cz = cb[2 * MM + m];
    float c2 = __fadd_rn(__fadd_rn(__fmul_rn(cx, cx), __fmul_rn(cy, cy)),
                         __fmul_rn(cz, cz));

    int ci = cell_of(cx), cj = cell_of(cy), ck = cell_of(cz);
    int i0 = max(ci - 1, 0), i1 = min(ci + 1, 9);
    int j0 = max(cj - 1, 0), j1 = min(cj + 1, 9);
    int k0 = max(ck - 1, 0), k1 = min(ck + 1, 9);

    const float4* bpt = g_bpt + (size_t)b * NN;
    const int* st     = g_start + b * (NCELL + 1);

    unsigned below = (1u << lane) - 1u;
    int cnt = 0;

    for (int i = i0; i <= i1; i++) {
        // branchless lower bound on |x - cx| for points in cell-column i
        float bx = i * 0.1f;
        float dxl = fmaxf(fmaxf(bx - cx, cx - (bx + 0.1f)), 0.0f);
        for (int j = j0; j <= j1; j++) {
            float by = j * 0.1f;
            float dyl = fmaxf(fmaxf(by - cy, cy - (by + 0.1f)), 0.0f);
            float d2xy = dxl * dxl + dyl * dyl;
            if (d2xy >= R2P) continue;                 // column unreachable
            // conservative reachable z-window (cannot drop a reference hit)
            float dzm = sqrtf(R2P - d2xy) + 2e-5f;
            int kk0 = max(k0, __float2int_rd((cz - dzm) * 10.0f));
            int kk1 = min(k1, __float2int_rd((cz + dzm) * 10.0f));

            int cbase = (i * GC + j) * GC;
            int s = st[cbase + kk0];
            int e = st[cbase + kk1 + 1];    // k-range contiguous in bins
            for (int p0 = s; p0 < e; p0 += 32) {
                int p = p0 + lane;
                bool hit = false;
                float4 v;
                if (p < e) {
                    v = __ldg(bpt + p);
                    // reference p2: (x*x + y*y) + z*z, individually rounded
                    float p2 = __fadd_rn(__fadd_rn(__fmul_rn(v.x, v.x),
                                                   __fmul_rn(v.y, v.y)),
                                         __fmul_rn(v.z, v.z));
                    // reference inner: cuBLAS k=3 FMA chain
                    float inner = __fmaf_rn(cz, v.z,
                                  __fmaf_rn(cy, v.y, __fmul_rn(cx, v.x)));
                    float d2 = __fsub_rn(__fadd_rn(c2, p2),
                                         __fmul_rn(2.0f, inner));
                    hit = d2 < R2C;
                }
                unsigned wm = __ballot_sync(0xffffffffu, hit);
                if (hit) {
                    int rank = cnt + __popc(wm & below);
                    if (rank < 128) hb[rank] = __float_as_int(v.w);
                }
                cnt += __popc(wm);
            }
        }
    }
    __syncwarp();

    // ---- adaptive top-32 smallest (ascending) into h0; pads = IMAX ----
    int h0 = (lane < cnt) ? hb[lane] : IMAX;
    sort32(h0, lane);
    if (cnt > 32) {
        int h1 = (lane + 32 < cnt) ? hb[lane + 32] : IMAX;
        sort32(h1, lane);
        if (cnt > 64) {
            int h2 = (lane + 64 < cnt) ? hb[lane + 64] : IMAX;
            sort32(h2, lane);
            if (cnt > 96) {
                int h3 = (lane + 96 < cnt) ? hb[lane + 96] : IMAX;
                sort32(h3, lane);
                merge_min32(h2, h3, lane);
            }
            merge_min32(h0, h1, lane);
            merge_min32(h0, h2, lane);
        } else {
            merge_min32(h0, h1, lane);
        }
    }

    int myidx = h0;
    int first = __shfl_sync(0xffffffffu, h0, 0);
    if (first == IMAX) first = 0;
    if (myidx == IMAX) myidx = first;          // lane k = neighbor for slot k

    // ---- direct gather: lane = output slot k; batched loads for MLP ----
    const float4* r4 = (const float4*)(g_t + ((size_t)b * NN + myidx) * ROW);

    const size_t CH = (size_t)MM * KK;
    size_t ob = (((size_t)b * 67) * MM + m) * KK + lane;

    {
        float4 w[9];
        #pragma unroll
        for (int q = 0; q < 9; q++) w[q] = __ldg(r4 + q);   // w[0] = xyz,pad
        out[ob]          = __fsub_rn(w[0].x, cx);
        out[ob + CH]     = __fsub_rn(w[0].y, cy);
        out[ob + 2 * CH] = __fsub_rn(w[0].z, cz);
        #pragma unroll
        for (int q = 1; q < 9; q++) {
            size_t o = ob + (size_t)(4 * q - 1) * CH;       // channels 4q-1..4q+2
            out[o]          = w[q].x;
            out[o + CH]     = w[q].y;
            out[o + 2 * CH] = w[q].z;
            out[o + 3 * CH] = w[q].w;
        }
    }
    {
        float4 u[8];
        #pragma unroll
        for (int q = 0; q < 8; q++) u[q] = __ldg(r4 + 9 + q);
        #pragma unroll
        for (int q = 0; q < 8; q++) {
            size_t o = ob + (size_t)(35 + 4 * q) * CH;      // channels 35..66
            out[o]          = u[q].x;
            out[o + CH]     = u[q].y;
            out[o + 2 * CH] = u[q].z;
            out[o + 3 * CH] = u[q].w;
        }
    }
}

// ---------------------------------------------------------------------------
extern "C" void kernel_launch(void* const* d_in, const int* in_sizes, int n_in,
                              void* d_out, int out_size)
{
    const float* pc = (const float*)d_in[0];   // points_coords  (B,3,N)
    const float* cc = (const float*)d_in[1];   // centers_coords (B,3,M)
    const float* pf = (const float*)d_in[2];   // points_features(B,C,N)
    float* out = (float*)d_out;                // (B, 67, M, K)

    dim3 tgrid(NN / 64, BB);
    transpose_kernel<<<tgrid, 256>>>(pc, pf);
    scan_kernel<<<BB, 1024>>>();
    scatter_kernel<<<(BB * NN) / (256 * 4), 256>>>(pc);
    query_kernel<<<BB * MM / 8, 256>>>(cc, out);
}

// round 15
// speedup vs baseline: 1.2125x; 1.0435x over previous
#include <cuda_runtime.h>

#define BB 4
#define NN 16384
#define MM 2048
#define CC 64
#define KK 32
#define ROW 68            // xyz, pad, 64 features
#define R2C 0.01f
#define GC 10
#define NCELL 1000
#define IMAX 0x7fffffff

// Transposed rows for grouping gather: [b][n][0..2]=xyz, [3]=pad, [4..67]=features
__device__ __align__(16) float g_t[(size_t)BB * NN * ROW];
// Grid-binned points: (x, y, z, index-as-float-bits)
__device__ __align__(16) float4 g_bpt[BB * NN];
__device__ int g_cnt[BB * NCELL];          // zero-init; re-zeroed by scan_kernel
__device__ int g_start[BB * (NCELL + 1)];
__device__ int g_rk[BB * NN];              // per-point: cell*16384 + within-cell rank

__device__ __forceinline__ int cell_of(float x) {
    int c = (int)(x * 10.0f);
    return c < 0 ? 0 : (c > 9 ? 9 : c);
}

// ---------------------------------------------------------------------------
// K1: transpose (B,3,N)+(B,C,N) -> (B,N,68) rows; fused histogram + rank
// ---------------------------------------------------------------------------
__global__ void __launch_bounds__(256) transpose_kernel(
    const float* __restrict__ pc, const float* __restrict__ pf)
{
    __shared__ float tile[67][65];
    int b  = blockIdx.y;
    int n0 = blockIdx.x * 64;

    const float* src_c = pc + (size_t)b * 3 * NN;
    const float* src_f = pf + (size_t)b * CC * NN;

    // float4 loads along n
    for (int i = threadIdx.x; i < 67 * 16; i += 256) {
        int c = i >> 4, q = i & 15;
        const float* s = (c < 3) ? (src_c + (size_t)c * NN)
                                 : (src_f + (size_t)(c - 3) * NN);
        float4 v = *(const float4*)(s + n0 + q * 4);
        tile[c][q * 4 + 0] = v.x; tile[c][q * 4 + 1] = v.y;
        tile[c][q * 4 + 2] = v.z; tile[c][q * 4 + 3] = v.w;
    }
    __syncthreads();

    // fused histogram: atomic returns within-cell rank; save cell+rank per point
    if (threadIdx.x < 64) {
        int t = threadIdx.x;
        float x = tile[0][t], y = tile[1][t], z = tile[2][t];
        int cell = (cell_of(x) * GC + cell_of(y)) * GC + cell_of(z);
        int rank = atomicAdd(&g_cnt[b * NCELL + cell], 1);
        g_rk[b * NN + n0 + t] = cell * 16384 + rank;
    }

    // float4 stores along the 68-float row (row = 272B, 16B aligned)
    float* dst = g_t + ((size_t)b * NN + n0) * ROW;
    for (int i = threadIdx.x; i < 64 * 17; i += 256) {
        int nl = i / 17, q = i % 17;
        float4 v;
        if (q == 0) { v.x = tile[0][nl]; v.y = tile[1][nl]; v.z = tile[2][nl]; v.w = 0.0f; }
        else { v.x = tile[4*q-1][nl]; v.y = tile[4*q][nl]; v.z = tile[4*q+1][nl]; v.w = tile[4*q+2][nl]; }
        *(float4*)(dst + (size_t)nl * ROW + q * 4) = v;
    }
}

// ---------------------------------------------------------------------------
// K2: exclusive scan per batch (1 block/batch); re-zeroes g_cnt for next run
// ---------------------------------------------------------------------------
__global__ void __launch_bounds__(1024) scan_kernel()
{
    __shared__ int s[NCELL];
    int b = blockIdx.x, t = threadIdx.x;
    int myc = 0;
    if (t < NCELL) {
        myc = g_cnt[b * NCELL + t];
        g_cnt[b * NCELL + t] = 0;      // restore invariant for next replay
        s[t] = myc;
    }
    __syncthreads();
    for (int off = 1; off < NCELL; off <<= 1) {
        int v = 0;
        if (t < NCELL && t >= off) v = s[t - off];
        __syncthreads();
        if (t < NCELL) s[t] += v;
        __syncthreads();
    }
    if (t < NCELL) g_start[b * (NCELL + 1) + t] = s[t] - myc;
    if (t == 0)    g_start[b * (NCELL + 1) + NCELL] = NN;
}

// ---------------------------------------------------------------------------
// K3: scatter — atomic-free, 4 points/thread with front-batched loads (ILP)
// ---------------------------------------------------------------------------
__global__ void __launch_bounds__(256) scatter_kernel(const float* __restrict__ pc)
{
    int t = blockIdx.x * 256 + threadIdx.x;    // 0..16383
    // 4 independent points: p = t + i*16384 ; b = p>>14, n = p&16383
    int   rk[4];
    float x[4], y[4], z[4];
    #pragma unroll
    for (int i = 0; i < 4; i++) {
        int p = t + i * 16384;
        rk[i] = __ldg(g_rk + p);
        int b = p >> 14, n = p & 16383;
        const float* base = pc + (size_t)b * 3 * NN;
        x[i] = __ldg(base + n);
        y[i] = __ldg(base + NN + n);
        z[i] = __ldg(base + 2 * NN + n);
    }
    #pragma unroll
    for (int i = 0; i < 4; i++) {
        int p = t + i * 16384;
        int b = p >> 14, n = p & 16383;
        int cell = rk[i] >> 14;
        int rank = rk[i] & 16383;
        int pos  = __ldg(g_start + b * (NCELL + 1) + cell) + rank;
        g_bpt[b * NN + pos] = make_float4(x[i], y[i], z[i], __int_as_float(n));
    }
}

// ---------------------------------------------------------------------------
// Warp bitonic helpers (32 elems across lanes)
// ---------------------------------------------------------------------------
__device__ __forceinline__ void bstage(int& h, int lane, int j, int k)
{
    int o = __shfl_xor_sync(0xffffffffu, h, j);
    bool asc   = (lane & k) == 0;
    bool lower = (lane & j) == 0;
    h = (lower == asc) ? min(h, o) : max(h, o);
}
__device__ __forceinline__ void sort32(int& h, int lane)
{
    bstage(h, lane, 1, 2);
    bstage(h, lane, 2, 4);  bstage(h, lane, 1, 4);
    bstage(h, lane, 4, 8);  bstage(h, lane, 2, 8);  bstage(h, lane, 1, 8);
    bstage(h, lane, 8, 16); bstage(h, lane, 4, 16); bstage(h, lane, 2, 16); bstage(h, lane, 1, 16);
    bstage(h, lane, 16, 32); bstage(h, lane, 8, 32); bstage(h, lane, 4, 32);
    bstage(h, lane, 2, 32);  bstage(h, lane, 1, 32);
}
__device__ __forceinline__ void clean32(int& h, int lane)
{
    #pragma unroll
    for (int j = 16; j >= 1; j >>= 1) {
        int o = __shfl_xor_sync(0xffffffffu, h, j);
        h = ((lane & j) == 0) ? min(h, o) : max(h, o);
    }
}
__device__ __forceinline__ void merge_min32(int& a, int b, int lane)
{
    int br = __shfl_sync(0xffffffffu, b, 31 ^ lane);  // b reversed
    a = min(a, br);                                   // bitonic
    clean32(a, lane);
}

// ---------------------------------------------------------------------------
// K4: FUSED warp-per-center (R12 query body), 64-thread blocks:
//     block = 2 warps -> near-warp retirement granularity, less tail waste
// ---------------------------------------------------------------------------
__global__ void __launch_bounds__(64, 16) query_kernel(
    const float* __restrict__ cc, float* __restrict__ out)
{
    __shared__ int hits[2][128];
    int wib  = threadIdx.x >> 5;
    int lane = threadIdx.x & 31;
    int* hb  = hits[wib];

    int gw = blockIdx.x * 2 + wib;
    int b = gw / MM;
    int m = gw % MM;

    const float* cb = cc + (size_t)b * 3 * MM;
    float cx = cb[m], cy = cb[MM + m], cz = cb[2 * MM + m];
    float c2 = __fadd_rn(__fadd_rn(__fmul_rn(cx, cx), __fmul_rn(cy, cy)),
                         __fmul_rn(cz, cz));

    int ci = cell_of(cx), cj = cell_of(cy), ck = cell_of(cz);
    int i0 = max(ci - 1, 0), i1 = min(ci + 1, 9);
    int j0 = max(cj - 1, 0), j1 = min(cj + 1, 9);
    int k0 = max(ck - 1, 0), k1 = min(ck + 1, 9);

    const float4* bpt = g_bpt + (size_t)b * NN;
    const int* st     = g_start + b * (NCELL + 1);

    unsigned below = (1u << lane) - 1u;
    int cnt = 0;

    for (int i = i0; i <= i1; i++) {
        for (int j = j0; j <= j1; j++) {
            int cbase = (i * GC + j) * GC;
            int s = st[cbase + k0];
            int e = st[cbase + k1 + 1];     // k-range contiguous in bins
            for (int p0 = s; p0 < e; p0 += 32) {
                int p = p0 + lane;
                bool hit = false;
                float4 v;
                if (p < e) {
                    v = __ldg(bpt + p);
                    // reference p2: (x*x + y*y) + z*z, individually rounded
                    float p2 = __fadd_rn(__fadd_rn(__fmul_rn(v.x, v.x),
                                                   __fmul_rn(v.y, v.y)),
                                         __fmul_rn(v.z, v.z));
                    // reference inner: cuBLAS k=3 FMA chain
                    float inner = __fmaf_rn(cz, v.z,
                                  __fmaf_rn(cy, v.y, __fmul_rn(cx, v.x)));
                    float d2 = __fsub_rn(__fadd_rn(c2, p2),
                                         __fmul_rn(2.0f, inner));
                    hit = d2 < R2C;
                }
                unsigned wm = __ballot_sync(0xffffffffu, hit);
                if (hit) {
                    int rank = cnt + __popc(wm & below);
                    if (rank < 128) hb[rank] = __float_as_int(v.w);
                }
                cnt += __popc(wm);
            }
        }
    }
    __syncwarp();

    // ---- adaptive top-32 smallest (ascending) into h0; pads = IMAX ----
    int h0 = (lane < cnt) ? hb[lane] : IMAX;
    sort32(h0, lane);
    if (cnt > 32) {
        int h1 = (lane + 32 < cnt) ? hb[lane + 32] : IMAX;
        sort32(h1, lane);
        if (cnt > 64) {
            int h2 = (lane + 64 < cnt) ? hb[lane + 64] : IMAX;
            sort32(h2, lane);
            if (cnt > 96) {
                int h3 = (lane + 96 < cnt) ? hb[lane + 96] : IMAX;
                sort32(h3, lane);
                merge_min32(h2, h3, lane);
            }
            merge_min32(h0, h1, lane);
            merge_min32(h0, h2, lane);
        } else {
            merge_min32(h0, h1, lane);
        }
    }

    int myidx = h0;
    int first = __shfl_sync(0xffffffffu, h0, 0);
    if (first == IMAX) first = 0;
    if (myidx == IMAX) myidx = first;          // lane k = neighbor for slot k

    // ---- direct gather: lane = output slot k; batched loads for MLP ----
    const float4* r4 = (const float4*)(g_t + ((size_t)b * NN + myidx) * ROW);

    const size_t CH = (size_t)MM * KK;
    size_t ob = (((size_t)b * 67) * MM + m) * KK + lane;

    {
        float4 w[9];
        #pragma unroll
        for (int q = 0; q < 9; q++) w[q] = __ldg(r4 + q);   // w[0] = xyz,pad
        out[ob]          = __fsub_rn(w[0].x, cx);
        out[ob + CH]     = __fsub_rn(w[0].y, cy);
        out[ob + 2 * CH] = __fsub_rn(w[0].z, cz);
        #pragma unroll
        for (int q = 1; q < 9; q++) {
            size_t o = ob + (size_t)(4 * q - 1) * CH;       // channels 4q-1..4q+2
            out[o]          = w[q].x;
            out[o + CH]     = w[q].y;
            out[o + 2 * CH] = w[q].z;
            out[o + 3 * CH] = w[q].w;
        }
    }
    {
        float4 u[8];
        #pragma unroll
        for (int q = 0; q < 8; q++) u[q] = __ldg(r4 + 9 + q);
        #pragma unroll
        for (int q = 0; q < 8; q++) {
            size_t o = ob + (size_t)(35 + 4 * q) * CH;      // channels 35..66
            out[o]          = u[q].x;
            out[o + CH]     = u[q].y;
            out[o + 2 * CH] = u[q].z;
            out[o + 3 * CH] = u[q].w;
        }
    }
}

// ---------------------------------------------------------------------------
extern "C" void kernel_launch(void* const* d_in, const int* in_sizes, int n_in,
                              void* d_out, int out_size)
{
    const float* pc = (const float*)d_in[0];   // points_coords  (B,3,N)
    const float* cc = (const float*)d_in[1];   // centers_coords (B,3,M)
    const float* pf = (const float*)d_in[2];   // points_features(B,C,N)
    float* out = (float*)d_out;                // (B, 67, M, K)

    dim3 tgrid(NN / 64, BB);
    transpose_kernel<<<tgrid, 256>>>(pc, pf);
    scan_kernel<<<BB, 1024>>>();
    scatter_kernel<<<(BB * NN) / (256 * 4), 256>>>(pc);
    query_kernel<<<BB * MM / 2, 64>>>(cc, out);
}

// round 16
// speedup vs baseline: 1.2193x; 1.0056x over previous
#include <cuda_runtime.h>

#define BB 4
#define NN 16384
#define MM 2048
#define CC 64
#define KK 32
#define ROW 68            // xyz, pad, 64 features
#define R2C 0.01f
#define GC 10
#define NCELL 1000
#define IMAX 0x7fffffff

// Transposed rows for grouping gather: [b][n][0..2]=xyz, [3]=pad, [4..67]=features
__device__ __align__(16) float g_t[(size_t)BB * NN * ROW];
// Grid-binned points: (x, y, z, index-as-float-bits)
__device__ __align__(16) float4 g_bpt[BB * NN];
__device__ int g_cnt[BB * NCELL];          // zero-init; re-zeroed by scan_kernel
__device__ int g_start[BB * (NCELL + 1)];
__device__ int g_rk[BB * NN];              // per-point: cell*16384 + within-cell rank

__device__ __forceinline__ int cell_of(float x) {
    int c = (int)(x * 10.0f);
    return c < 0 ? 0 : (c > 9 ? 9 : c);
}

// ---------------------------------------------------------------------------
// K1: transpose (B,3,N)+(B,C,N) -> (B,N,68) rows; fused histogram + rank
// ---------------------------------------------------------------------------
__global__ void __launch_bounds__(256) transpose_kernel(
    const float* __restrict__ pc, const float* __restrict__ pf)
{
    __shared__ float tile[67][65];
    int b  = blockIdx.y;
    int n0 = blockIdx.x * 64;

    const float* src_c = pc + (size_t)b * 3 * NN;
    const float* src_f = pf + (size_t)b * CC * NN;

    // float4 loads along n
    for (int i = threadIdx.x; i < 67 * 16; i += 256) {
        int c = i >> 4, q = i & 15;
        const float* s = (c < 3) ? (src_c + (size_t)c * NN)
                                 : (src_f + (size_t)(c - 3) * NN);
        float4 v = *(const float4*)(s + n0 + q * 4);
        tile[c][q * 4 + 0] = v.x; tile[c][q * 4 + 1] = v.y;
        tile[c][q * 4 + 2] = v.z; tile[c][q * 4 + 3] = v.w;
    }
    __syncthreads();

    // fused histogram: atomic returns within-cell rank; save cell+rank per point
    if (threadIdx.x < 64) {
        int t = threadIdx.x;
        float x = tile[0][t], y = tile[1][t], z = tile[2][t];
        int cell = (cell_of(x) * GC + cell_of(y)) * GC + cell_of(z);
        int rank = atomicAdd(&g_cnt[b * NCELL + cell], 1);
        g_rk[b * NN + n0 + t] = cell * 16384 + rank;
    }

    // float4 stores along the 68-float row (row = 272B, 16B aligned)
    float* dst = g_t + ((size_t)b * NN + n0) * ROW;
    for (int i = threadIdx.x; i < 64 * 17; i += 256) {
        int nl = i / 17, q = i % 17;
        float4 v;
        if (q == 0) { v.x = tile[0][nl]; v.y = tile[1][nl]; v.z = tile[2][nl]; v.w = 0.0f; }
        else { v.x = tile[4*q-1][nl]; v.y = tile[4*q][nl]; v.z = tile[4*q+1][nl]; v.w = tile[4*q+2][nl]; }
        *(float4*)(dst + (size_t)nl * ROW + q * 4) = v;
    }
}

// ---------------------------------------------------------------------------
// K2: exclusive scan per batch (1 block/batch); re-zeroes g_cnt for next run
// ---------------------------------------------------------------------------
__global__ void __launch_bounds__(1024) scan_kernel()
{
    __shared__ int s[NCELL];
    int b = blockIdx.x, t = threadIdx.x;
    int myc = 0;
    if (t < NCELL) {
        myc = g_cnt[b * NCELL + t];
        g_cnt[b * NCELL + t] = 0;      // restore invariant for next replay
        s[t] = myc;
    }
    __syncthreads();
    for (int off = 1; off < NCELL; off <<= 1) {
        int v = 0;
        if (t < NCELL && t >= off) v = s[t - off];
        __syncthreads();
        if (t < NCELL) s[t] += v;
        __syncthreads();
    }
    if (t < NCELL) g_start[b * (NCELL + 1) + t] = s[t] - myc;
    if (t == 0)    g_start[b * (NCELL + 1) + NCELL] = NN;
}

// ---------------------------------------------------------------------------
// K3: scatter — atomic-free, 4 points/thread with front-batched loads (ILP)
// ---------------------------------------------------------------------------
__global__ void __launch_bounds__(256) scatter_kernel(const float* __restrict__ pc)
{
    int t = blockIdx.x * 256 + threadIdx.x;    // 0..16383
    int   rk[4];
    float x[4], y[4], z[4];
    #pragma unroll
    for (int i = 0; i < 4; i++) {
        int p = t + i * 16384;
        rk[i] = __ldg(g_rk + p);
        int b = p >> 14, n = p & 16383;
        const float* base = pc + (size_t)b * 3 * NN;
        x[i] = __ldg(base + n);
        y[i] = __ldg(base + NN + n);
        z[i] = __ldg(base + 2 * NN + n);
    }
    #pragma unroll
    for (int i = 0; i < 4; i++) {
        int p = t + i * 16384;
        int b = p >> 14, n = p & 16383;
        int cell = rk[i] >> 14;
        int rank = rk[i] & 16383;
        int pos  = __ldg(g_start + b * (NCELL + 1) + cell) + rank;
        g_bpt[b * NN + pos] = make_float4(x[i], y[i], z[i], __int_as_float(n));
    }
}

// ---------------------------------------------------------------------------
// Warp bitonic helpers (32 elems across lanes)
// ---------------------------------------------------------------------------
__device__ __forceinline__ void bstage(int& h, int lane, int j, int k)
{
    int o = __shfl_xor_sync(0xffffffffu, h, j);
    bool asc   = (lane & k) == 0;
    bool lower = (lane & j) == 0;
    h = (lower == asc) ? min(h, o) : max(h, o);
}
__device__ __forceinline__ void sort32(int& h, int lane)
{
    bstage(h, lane, 1, 2);
    bstage(h, lane, 2, 4);  bstage(h, lane, 1, 4);
    bstage(h, lane, 4, 8);  bstage(h, lane, 2, 8);  bstage(h, lane, 1, 8);
    bstage(h, lane, 8, 16); bstage(h, lane, 4, 16); bstage(h, lane, 2, 16); bstage(h, lane, 1, 16);
    bstage(h, lane, 16, 32); bstage(h, lane, 8, 32); bstage(h, lane, 4, 32);
    bstage(h, lane, 2, 32);  bstage(h, lane, 1, 32);
}
__device__ __forceinline__ void clean32(int& h, int lane)
{
    #pragma unroll
    for (int j = 16; j >= 1; j >>= 1) {
        int o = __shfl_xor_sync(0xffffffffu, h, j);
        h = ((lane & j) == 0) ? min(h, o) : max(h, o);
    }
}
__device__ __forceinline__ void merge_min32(int& a, int b, int lane)
{
    int br = __shfl_sync(0xffffffffu, b, 31 ^ lane);  // b reversed
    a = min(a, br);                                   // bitonic
    clean32(a, lane);
}

// ---------------------------------------------------------------------------
// K4: FUSED warp-per-center, 64-thread blocks, FLATTENED + PIPELINED search:
//     parallel range fetch (lanes 0..8) + 1-deep candidate-load prefetch
// ---------------------------------------------------------------------------
__global__ void __launch_bounds__(64, 16) query_kernel(
    const float* __restrict__ cc, float* __restrict__ out)
{
    __shared__ int hits[2][128];
    int wib  = threadIdx.x >> 5;
    int lane = threadIdx.x & 31;
    int* hb  = hits[wib];

    int gw = blockIdx.x * 2 + wib;
    int b = gw / MM;
    int m = gw % MM;

    const float* cb = cc + (size_t)b * 3 * MM;
    float cx = cb[m], cy = cb[MM + m], cz = cb[2 * MM + m];
    float c2 = __fadd_rn(__fadd_rn(__fmul_rn(cx, cx), __fmul_rn(cy, cy)),
                         __fmul_rn(cz, cz));

    int ci = cell_of(cx), cj = cell_of(cy), ck = cell_of(cz);
    int i0 = max(ci - 1, 0), i1 = min(ci + 1, 9);
    int j0 = max(cj - 1, 0), j1 = min(cj + 1, 9);
    int k0 = max(ck - 1, 0), k1 = min(ck + 1, 9);
    int nj = j1 - j0 + 1;
    int ncolTot = (i1 - i0 + 1) * nj;          // <= 9 candidate columns

    const float4* bpt = g_bpt + (size_t)b * NN;
    const int* st     = g_start + b * (NCELL + 1);

    // parallel range fetch: lane l < ncolTot owns column l's [s,e)
    int sreg = 0, ereg = 0;
    if (lane < ncolTot) {
        int ii = i0 + lane / nj;
        int jj = j0 + lane % nj;
        int cbase = (ii * GC + jj) * GC;
        sreg = __ldg(st + cbase + k0);
        ereg = __ldg(st + cbase + k1 + 1);     // k-range contiguous in bins
    }

    unsigned below = (1u << lane) - 1u;
    int cnt = 0;

    // ---- flattened, 1-deep pipelined scan over all columns ----
    int col = 0;
    int p0 = __shfl_sync(0xffffffffu, sreg, 0);
    int pe = __shfl_sync(0xffffffffu, ereg, 0);

    bool pv = (p0 + lane) < pe;
    float4 v;
    if (pv) v = __ldg(bpt + p0 + lane);

    while (true) {
        // compute next step's state
        int ncol2 = col, np0 = p0 + 32, npe = pe;
        if (np0 >= npe) {
            ncol2++;
            if (ncol2 < ncolTot) {
                np0 = __shfl_sync(0xffffffffu, sreg, ncol2);
                npe = __shfl_sync(0xffffffffu, ereg, ncol2);
            }
        }
        bool more = ncol2 < ncolTot;

        // prefetch next step's candidates
        bool pvn = false;
        float4 vn;
        if (more) {
            pvn = (np0 + lane) < npe;
            if (pvn) vn = __ldg(bpt + np0 + lane);
        }

        // process current step
        bool hit = false;
        if (pv) {
            // reference p2: (x*x + y*y) + z*z, individually rounded
            float p2 = __fadd_rn(__fadd_rn(__fmul_rn(v.x, v.x),
                                           __fmul_rn(v.y, v.y)),
                                 __fmul_rn(v.z, v.z));
            // reference inner: cuBLAS k=3 FMA chain
            float inner = __fmaf_rn(cz, v.z,
                          __fmaf_rn(cy, v.y, __fmul_rn(cx, v.x)));
            float d2 = __fsub_rn(__fadd_rn(c2, p2),
                                 __fmul_rn(2.0f, inner));
            hit = d2 < R2C;
        }
        unsigned wm = __ballot_sync(0xffffffffu, hit);
        if (hit) {
            int rank = cnt + __popc(wm & below);
            if (rank < 128) hb[rank] = __float_as_int(v.w);
        }
        cnt += __popc(wm);

        if (!more) break;
        col = ncol2; p0 = np0; pe = npe;
        v = vn; pv = pvn;
    }
    __syncwarp();

    // ---- adaptive top-32 smallest (ascending) into h0; pads = IMAX ----
    int h0 = (lane < cnt) ? hb[lane] : IMAX;
    sort32(h0, lane);
    if (cnt > 32) {
        int h1 = (lane + 32 < cnt) ? hb[lane + 32] : IMAX;
        sort32(h1, lane);
        if (cnt > 64) {
            int h2 = (lane + 64 < cnt) ? hb[lane + 64] : IMAX;
            sort32(h2, lane);
            if (cnt > 96) {
                int h3 = (lane + 96 < cnt) ? hb[lane + 96] : IMAX;
                sort32(h3, lane);
                merge_min32(h2, h3, lane);
            }
            merge_min32(h0, h1, lane);
            merge_min32(h0, h2, lane);
        } else {
            merge_min32(h0, h1, lane);
        }
    }

    int myidx = h0;
    int first = __shfl_sync(0xffffffffu, h0, 0);
    if (first == IMAX) first = 0;
    if (myidx == IMAX) myidx = first;          // lane k = neighbor for slot k

    // ---- direct gather: lane = output slot k; batched loads for MLP ----
    const float4* r4 = (const float4*)(g_t + ((size_t)b * NN + myidx) * ROW);

    const size_t CH = (size_t)MM * KK;
    size_t ob = (((size_t)b * 67) * MM + m) * KK + lane;

    {
        float4 w[9];
        #pragma unroll
        for (int q = 0; q < 9; q++) w[q] = __ldg(r4 + q);   // w[0] = xyz,pad
        out[ob]          = __fsub_rn(w[0].x, cx);
        out[ob + CH]     = __fsub_rn(w[0].y, cy);
        out[ob + 2 * CH] = __fsub_rn(w[0].z, cz);
        #pragma unroll
        for (int q = 1; q < 9; q++) {
            size_t o = ob + (size_t)(4 * q - 1) * CH;       // channels 4q-1..4q+2
            out[o]          = w[q].x;
            out[o + CH]     = w[q].y;
            out[o + 2 * CH] = w[q].z;
            out[o + 3 * CH] = w[q].w;
        }
    }
    {
        float4 u[8];
        #pragma unroll
        for (int q = 0; q < 8; q++) u[q] = __ldg(r4 + 9 + q);
        #pragma unroll
        for (int q = 0; q < 8; q++) {
            size_t o = ob + (size_t)(35 + 4 * q) * CH;      // channels 35..66
            out[o]          = u[q].x;
            out[o + CH]     = u[q].y;
            out[o + 2 * CH] = u[q].z;
            out[o + 3 * CH] = u[q].w;
        }
    }
}

// ---------------------------------------------------------------------------
extern "C" void kernel_launch(void* const* d_in, const int* in_sizes, int n_in,
                              void* d_out, int out_size)
{
    const float* pc = (const float*)d_in[0];   // points_coords  (B,3,N)
    const float* cc = (const float*)d_in[1];   // centers_coords (B,3,M)
    const float* pf = (const float*)d_in[2];   // points_features(B,C,N)
    float* out = (float*)d_out;                // (B, 67, M, K)

    dim3 tgrid(NN / 64, BB);
    transpose_kernel<<<tgrid, 256>>>(pc, pf);
    scan_kernel<<<BB, 1024>>>();
    scatter_kernel<<<(BB * NN) / (256 * 4), 256>>>(pc);
    query_kernel<<<BB * MM / 2, 64>>>(cc, out);
}